// round 4
// baseline (speedup 1.0000x reference)
#include <cuda_runtime.h>
#include <cuda_bf16.h>
#include <cstdint>

// ---------------------------------------------------------------------------
// AffinityHead — mma.sync (bf16 x3 split) tensor-core GEMM core, with the
// per-atom B-tile build software-pipelined (double-buffered) into the MMA
// mainloop so the tensor pipe never idles on builds.
// ---------------------------------------------------------------------------

__device__ __forceinline__ float silu_f(float v) { return v / (1.f + __expf(-v)); }

// ------------------------- scratch (static, no allocs) ---------------------
__device__ float g_tok[4 * 128 * 128];     // [n][j][h]
__device__ float g_S1[4 * 64 * 27];
__device__ float g_S0[4 * 32 * 27];
__device__ float g_p[4 * 256];
__device__ float g_pf[4 * 128];
__device__ float g_atoms[4 * 1024 * 128];  // [n][i][k]
__device__ float g_atom_e[4 * 1024];

// ------------------------------ PTX helpers --------------------------------
__device__ __forceinline__ uint32_t smem_to_u32(const void* p) {
    uint32_t a;
    asm("{ .reg .u64 t; cvta.to.shared.u64 t, %1; cvt.u32.u64 %0, t; }" : "=r"(a) : "l"(p));
    return a;
}

__device__ __forceinline__ void ldsm_x4(uint32_t* r, uint32_t addr) {
    asm volatile("ldmatrix.sync.aligned.m8n8.x4.shared.b16 {%0,%1,%2,%3}, [%4];"
                 : "=r"(r[0]), "=r"(r[1]), "=r"(r[2]), "=r"(r[3]) : "r"(addr));
}

__device__ __forceinline__ void mma_bf16(float* d, const uint32_t* a, const uint32_t* b) {
    asm volatile(
        "mma.sync.aligned.m16n8k16.row.col.f32.bf16.bf16.f32 "
        "{%0,%1,%2,%3}, {%4,%5,%6,%7}, {%8,%9}, {%0,%1,%2,%3};"
        : "+f"(d[0]), "+f"(d[1]), "+f"(d[2]), "+f"(d[3])
        : "r"(a[0]), "r"(a[1]), "r"(a[2]), "r"(a[3]), "r"(b[0]), "r"(b[1]));
}

// ------------------------------ k_tok --------------------------------------
__global__ void k_tok(const float* __restrict__ tf, const float* __restrict__ Wt,
                      const float* __restrict__ bt) {
    int row = blockIdx.x;
    int t = threadIdx.x;
    __shared__ float s[256];
    const float* x = tf + row * 256;
    for (int c = t; c < 256; c += 128) s[c] = silu_f(x[c]);
    __syncthreads();
    float acc = bt[t];
#pragma unroll 8
    for (int c = 0; c < 256; c++) acc += s[c] * Wt[c * 128 + t];
    g_tok[row * 128 + t] = acc;
}

// ------------------------------ k_S1 ----------------------------------------
__global__ void k_S1(const float* __restrict__ x) {
    int nc = blockIdx.x;
    int t = threadIdx.x;
    __shared__ float v[512];
    for (int i = t; i < 512; i += 128) v[i] = silu_f(x[nc * 512 + i]);
    __syncthreads();
    if (t < 27) {
        int kd = t / 9, kh = (t / 3) % 3, kw = t % 3;
        float s = 0.f;
        for (int d = 0; d < 6; d++)
            for (int h = 0; h < 6; h++)
                for (int w = 0; w < 6; w++)
                    s += v[(d + kd) * 64 + (h + kh) * 8 + (w + kw)];
        g_S1[nc * 27 + t] = s;
    }
}

// ------------------------------ k_S0 ----------------------------------------
__global__ void k_S0(const float* __restrict__ x) {
    int nc = blockIdx.x;
    int t = threadIdx.x;
    __shared__ float v[4096];
    __shared__ float rbuf[8];
    for (int i = t; i < 4096; i += 256) v[i] = silu_f(x[nc * 4096 + i]);
    __syncthreads();
    for (int k = 0; k < 27; k++) {
        int kd = k / 9, kh = (k / 3) % 3, kw = k % 3;
        float s = 0.f;
        for (int p = t; p < 2744; p += 256) {
            int d = p / 196;
            int r = p % 196;
            int hh = r / 14, ww = r % 14;
            s += v[(d + kd) * 256 + (hh + kh) * 16 + (ww + kw)];
        }
        for (int off = 16; off > 0; off >>= 1) s += __shfl_down_sync(0xffffffffu, s, off);
        if ((t & 31) == 0) rbuf[t >> 5] = s;
        __syncthreads();
        if (t == 0) {
            float tot = 0.f;
            for (int w = 0; w < 8; w++) tot += rbuf[w];
            g_S0[nc * 27 + k] = tot;
        }
        __syncthreads();
    }
}

// ------------------------------ k_pconv (warp-per-output) -------------------
__global__ void k_pconv(const float* __restrict__ Wc0, const float* __restrict__ bc0,
                        const float* __restrict__ Wc1, const float* __restrict__ bc1) {
    int b = blockIdx.x, t = threadIdx.x;   // 64 blocks x 256 threads
    int n = b >> 4, og = b & 15;
    __shared__ float s1[1728];
    __shared__ float s0[864];
    for (int i = t; i < 1728; i += 256) s1[i] = g_S1[n * 1728 + i];
    for (int i = t; i < 864; i += 256) s0[i] = g_S0[n * 864 + i];
    __syncthreads();
    int w = t >> 5, lane = t & 31;
    int o = og * 8 + w;
    float a0 = 0.f;
    for (int x = lane; x < 1728; x += 32) a0 += s1[x] * Wc0[o * 1728 + x];
    float a1 = 0.f;
    for (int x = lane; x < 864; x += 32) a1 += s0[x] * Wc1[o * 864 + x];
#pragma unroll
    for (int off = 16; off > 0; off >>= 1) {
        a0 += __shfl_down_sync(0xffffffffu, a0, off);
        a1 += __shfl_down_sync(0xffffffffu, a1, off);
    }
    if (lane == 0) {
        g_p[n * 256 + o] = a0 * (1.f / 216.f) + bc0[o];
        g_p[n * 256 + 128 + o] = a1 * (1.f / 2744.f) + bc1[o];
    }
}

// ------------------------------ k_pf ----------------------------------------
__global__ void k_pf(const float* __restrict__ Wp, const float* __restrict__ bp,
                     const float* __restrict__ Wcat, const float* __restrict__ bcat,
                     const float* __restrict__ Wgate, const float* __restrict__ bgate) {
    int n = blockIdx.x, t = threadIdx.x;
    __shared__ float sp[256];
    __shared__ float pin[384];
    for (int c = t; c < 256; c += 128) sp[c] = silu_f(g_p[n * 256 + c]);
    float ts = 0.f;
    for (int j = 0; j < 128; j++) ts += g_tok[(n * 128 + j) * 128 + t];
    __syncthreads();
    float pk = bp[t];
#pragma unroll 4
    for (int c = 0; c < 256; c++) pk += sp[c] * Wp[c * 128 + t];
    pin[t] = pk;
    pin[128 + t] = ts;
    pin[256 + t] = ts * (1.f / 128.f);
    __syncthreads();
    float c1 = bcat[t], g1 = bgate[t];
#pragma unroll 4
    for (int c = 0; c < 384; c++) {
        float z = pin[c];
        c1 += z * Wcat[c * 128 + t];
        g1 += z * Wgate[c * 128 + t];
    }
    g_pf[n * 128 + t] = c1 / (1.f + __expf(-g1));
}

// ------------------------------ k_atoms -------------------------------------
__global__ void k_atoms(const float* __restrict__ la, const float* __restrict__ Wa,
                        const float* __restrict__ ba) {
    int r0 = blockIdx.x * 8;
    int t = threadIdx.x;
    __shared__ float s[8][64];
    for (int i = t; i < 512; i += 128) s[i >> 6][i & 63] = la[r0 * 64 + i];
    __syncthreads();
    float b = ba[t];
    float acc[8];
#pragma unroll
    for (int r = 0; r < 8; r++) acc[r] = b;
    for (int c = 0; c < 64; c++) {
        float w = Wa[c * 128 + t];
#pragma unroll
        for (int r = 0; r < 8; r++) acc[r] += s[r][c] * w;
    }
#pragma unroll
    for (int r = 0; r < 8; r++) g_atoms[(r0 + r) * 128 + t] = acc[r];
}

// ------------------------------ k_inter (pipelined mma.sync) ----------------
// smem layout (bytes):
//   tok hi [128][136]h : 34816      tok lo : 34816
//   M buffers x2, each (hi|lo) = 69632            -> 139264
//   cv (wpe|wpg|bi) 1536, pe/pg bufs 2048, red 16
#define STH 0
#define STL 34816
#define SMB 69632
#define MBUF_BYTES 69632
#define SCV 208896
#define SPE 210432
#define SRED 212480
#define SMEM_TC_BYTES 212512

// build one (h, k-pair) element of M = diag(a)*W into mb (hi plane @0, lo @34816)
__device__ __forceinline__ void build_elem(char* mb, const float* __restrict__ Wi,
                                           const float* __restrict__ avG, int p) {
    const int h = p & 127, kp = p >> 7;
    float w0 = Wi[(2 * kp) * 128 + h];
    float w1 = Wi[(2 * kp + 1) * 128 + h];
    float v0 = avG[2 * kp] * w0;
    float v1 = avG[2 * kp + 1] * w1;
    __nv_bfloat162 hi = __float22bfloat162_rn(make_float2(v0, v1));
    float r0 = v0 - __low2float(hi);
    float r1 = v1 - __high2float(hi);
    __nv_bfloat162 lo = __float22bfloat162_rn(make_float2(r0, r1));
    uint32_t off = (uint32_t)(h * 272 + kp * 4);
    *(__nv_bfloat162*)(mb + off) = hi;
    *(__nv_bfloat162*)(mb + 34816 + off) = lo;
}

__global__ void __launch_bounds__(256, 1)
k_inter(const float* __restrict__ Wi, const float* __restrict__ bi,
        const float* __restrict__ wpe, const float* __restrict__ bpe,
        const float* __restrict__ wpg, const float* __restrict__ bpg) {
    extern __shared__ char smc[];
    const uint32_t sb = smem_to_u32(smc);
    float* cv = (float*)(smc + SCV);
    float* peb = (float*)(smc + SPE);        // [2][128]
    float* pgb = peb + 256;                  // [2][128]
    float* red = (float*)(smc + SRED);

    const int t = threadIdx.x;
    const int wid = t >> 5;
    const int lane = t & 31;

    const int n = blockIdx.x / 37;
    const int grp = blockIdx.x % 37;
    const int i0 = grp * 28;
    const int cnt = min(28, 1024 - i0);
    const float* atomBase = g_atoms + (n * 1024 + i0) * 128;

    if (t < 128) {
        cv[t] = wpe[t];
        cv[128 + t] = wpg[t];
        cv[256 + t] = bi[t];
    }
    const float bpe0 = bpe[0], bpg0 = bpg[0];

    // ---- build tok hi/lo planes (A operand), once per block ----
    const float* tokn = g_tok + n * 16384;
    for (int p = t; p < 8192; p += 256) {
        int j = p >> 6, k2 = p & 63;
        float2 v = *(const float2*)(tokn + j * 128 + 2 * k2);
        __nv_bfloat162 hi = __float22bfloat162_rn(make_float2(v.x, v.y));
        float r0 = v.x - __low2float(hi);
        float r1 = v.y - __high2float(hi);
        __nv_bfloat162 lo = __float22bfloat162_rn(make_float2(r0, r1));
        uint32_t off = (uint32_t)(j * 272 + 4 * k2);
        *(__nv_bfloat162*)(smc + STH + off) = hi;
        *(__nv_bfloat162*)(smc + STL + off) = lo;
    }

    // ---- prologue: build M(0) into buffer 0 ----
    for (int p = t; p < 8192; p += 256) build_elem(smc + SMB, Wi, atomBase, p);
    __syncthreads();

    // ---- per-warp tile / ldmatrix lane addresses ----
    const int j0 = (wid & 3) * 32;   // 32 token rows per warp
    const int h0 = (wid >> 2) * 64;  // 64 h cols per warp-half

    const int aRow = lane & 15;
    const int aK = (lane >> 4) << 3;
    const uint32_t aOffH = sb + STH + (uint32_t)((j0 + aRow) * 272 + aK * 2);
    const uint32_t aOffL = sb + STL + (uint32_t)((j0 + aRow) * 272 + aK * 2);
    const int bRow = ((lane >> 4) << 3) + (lane & 7);
    const int bK = ((lane >> 3) & 1) << 3;
    const uint32_t bLane = (uint32_t)((h0 + bRow) * 272 + bK * 2);

    for (int a = 0; a < cnt; a++) {
        const uint32_t bBaseH = sb + SMB + (uint32_t)((a & 1) * MBUF_BYTES) + bLane;
        const uint32_t bBaseL = bBaseH + 34816;
        const bool doBuild = (a + 1 < cnt);
        char* mbN = smc + SMB + ((a + 1) & 1) * MBUF_BYTES;
        const float* avN = atomBase + (a + 1) * 128;

        float acc[2][8][4];
#pragma unroll
        for (int mt = 0; mt < 2; mt++)
#pragma unroll
            for (int nt = 0; nt < 8; nt++)
#pragma unroll
                for (int e = 0; e < 4; e++) acc[mt][nt][e] = 0.f;

#pragma unroll
        for (int ks = 0; ks < 8; ks++) {
            const uint32_t ko = (uint32_t)(ks * 32);
            uint32_t aH[2][4], aL[2][4], bH[4][4], bL[4][4];
            ldsm_x4(aH[0], aOffH + ko);
            ldsm_x4(aH[1], aOffH + 4352 + ko);
            ldsm_x4(aL[0], aOffL + ko);
            ldsm_x4(aL[1], aOffL + 4352 + ko);
#pragma unroll
            for (int ng = 0; ng < 4; ng++) {
                ldsm_x4(bH[ng], bBaseH + (uint32_t)(ng * 4352) + ko);
                ldsm_x4(bL[ng], bBaseL + (uint32_t)(ng * 4352) + ko);
            }
#pragma unroll
            for (int mt = 0; mt < 2; mt++) {
#pragma unroll
                for (int ng = 0; ng < 4; ng++) {
                    mma_bf16(acc[mt][2 * ng], aH[mt], bH[ng]);
                    mma_bf16(acc[mt][2 * ng + 1], aH[mt], bH[ng] + 2);
                    mma_bf16(acc[mt][2 * ng], aH[mt], bL[ng]);
                    mma_bf16(acc[mt][2 * ng + 1], aH[mt], bL[ng] + 2);
                    mma_bf16(acc[mt][2 * ng], aL[mt], bH[ng]);
                    mma_bf16(acc[mt][2 * ng + 1], aL[mt], bH[ng] + 2);
                }
            }
            // pipelined build of next atom's M tile (hidden under HMMA recycle)
            if (doBuild) {
#pragma unroll
                for (int u = 0; u < 4; u++)
                    build_elem(mbN, Wi, avN, t + (ks * 4 + u) * 256);
            }
        }

        // ---- epilogue: lrelu + pe/pg dots, per-row partials ----
        float pe[4] = {0.f, 0.f, 0.f, 0.f}, pg[4] = {0.f, 0.f, 0.f, 0.f};
#pragma unroll
        for (int nt = 0; nt < 8; nt++) {
#pragma unroll
            for (int c = 0; c < 2; c++) {
                const int h = h0 + 8 * nt + 2 * (lane & 3) + c;
                const float wpeh = cv[h];
                const float wpgh = cv[128 + h];
                const float bih = cv[256 + h];
#pragma unroll
                for (int mt = 0; mt < 2; mt++) {
#pragma unroll
                    for (int hf = 0; hf < 2; hf++) {
                        float v = acc[mt][nt][hf * 2 + c] + bih;
                        v = (v > 0.f) ? v : 0.01f * v;
                        pe[mt * 2 + hf] += v * wpeh;
                        pg[mt * 2 + hf] += v * wpgh;
                    }
                }
            }
        }
#pragma unroll
        for (int rs = 0; rs < 4; rs++) {
#pragma unroll
            for (int off = 1; off < 4; off <<= 1) {
                pe[rs] += __shfl_xor_sync(0xffffffffu, pe[rs], off);
                pg[rs] += __shfl_xor_sync(0xffffffffu, pg[rs], off);
            }
        }
        if ((lane & 3) == 0) {
            const int wx = wid >> 2;
#pragma unroll
            for (int mt = 0; mt < 2; mt++)
#pragma unroll
                for (int hf = 0; hf < 2; hf++) {
                    int j = j0 + 16 * mt + 8 * hf + (lane >> 2);
                    peb[wx * 128 + j] = pe[mt * 2 + hf];
                    pgb[wx * 128 + j] = pg[mt * 2 + hf];
                }
        }
        __syncthreads();

        if (t < 128) {
            float spe = peb[t] + peb[128 + t] + bpe0;
            float spg = pgb[t] + pgb[128 + t] + bpg0;
            float sj = spe / (1.f + __expf(-spg));
#pragma unroll
            for (int off = 16; off > 0; off >>= 1)
                sj += __shfl_xor_sync(0xffffffffu, sj, off);
            if (lane == 0) red[wid] = sj;
        }
        __syncthreads();
        if (t == 0) g_atom_e[n * 1024 + i0 + a] = red[0] + red[1] + red[2] + red[3];
        __syncthreads();
    }
}

// ------------------------------ k_final -------------------------------------
__global__ void k_final(const float* __restrict__ lgr, const int* __restrict__ lb,
                        const float* __restrict__ Wgr, const float* __restrict__ bgr,
                        const float* __restrict__ Wb1, const float* __restrict__ bb1,
                        const float* __restrict__ Wb2, const float* __restrict__ bb2,
                        float* __restrict__ out) {
    int n = blockIdx.x >> 6, g = blockIdx.x & 63, t = threadIdx.x;
    __shared__ float z[256];
    __shared__ float lg[64];
    __shared__ float red[8];
    if (t < 64) lg[t] = lgr[(n * 64 + g) * 64 + t];
    z[t] = g_pf[n * 128 + t];
    __syncthreads();
    float gf = bgr[t];
#pragma unroll 4
    for (int c = 0; c < 64; c++) gf += lg[c] * Wgr[c * 128 + t];
    z[128 + t] = gf;
    __syncthreads();
    float h = bb1[t];
#pragma unroll 4
    for (int c = 0; c < 256; c++) h += z[c] * Wb1[c * 128 + t];
    h = (h > 0.f) ? h : 0.01f * h;
    float part = h * Wb2[t];
    float seg = 0.f;
    for (int a = t; a < 1024; a += 128) {
        if (lb[a] == g) seg += g_atom_e[n * 1024 + a];
    }
#pragma unroll
    for (int off = 16; off > 0; off >>= 1) {
        part += __shfl_down_sync(0xffffffffu, part, off);
        seg += __shfl_down_sync(0xffffffffu, seg, off);
    }
    int wid = t >> 5;
    if ((t & 31) == 0) {
        red[wid] = part;
        red[4 + wid] = seg;
    }
    __syncthreads();
    if (t == 0) {
        float bias = red[0] + red[1] + red[2] + red[3] + bb2[0];
        float segs = red[4] + red[5] + red[6] + red[7];
        out[n * 64 + g] = segs + bias;
    }
}

// ------------------------------ launch --------------------------------------
extern "C" void kernel_launch(void* const* d_in, const int* in_sizes, int n_in,
                              void* d_out, int out_size) {
    const float* ms0 = (const float*)d_in[0];
    const float* ms1 = (const float*)d_in[1];
    const float* tf = (const float*)d_in[2];
    const float* lat = (const float*)d_in[3];
    const float* lgr = (const float*)d_in[4];
    const int* lb = (const int*)d_in[5];
    const float* Wt = (const float*)d_in[6];
    const float* bt = (const float*)d_in[7];
    const float* Wc0 = (const float*)d_in[8];
    const float* bc0 = (const float*)d_in[9];
    const float* Wc1 = (const float*)d_in[10];
    const float* bc1 = (const float*)d_in[11];
    const float* Wp = (const float*)d_in[12];
    const float* bp = (const float*)d_in[13];
    const float* Wcat = (const float*)d_in[14];
    const float* bcat = (const float*)d_in[15];
    const float* Wgate = (const float*)d_in[16];
    const float* bgate = (const float*)d_in[17];
    const float* Wa = (const float*)d_in[18];
    const float* ba = (const float*)d_in[19];
    const float* Wgr = (const float*)d_in[20];
    const float* bgr = (const float*)d_in[21];
    const float* Wb1 = (const float*)d_in[22];
    const float* bb1 = (const float*)d_in[23];
    const float* Wb2 = (const float*)d_in[24];
    const float* bb2 = (const float*)d_in[25];
    const float* Wi = (const float*)d_in[26];
    const float* bi = (const float*)d_in[27];
    const float* wpe = (const float*)d_in[28];
    const float* bpe = (const float*)d_in[29];
    const float* wpg = (const float*)d_in[30];
    const float* bpg = (const float*)d_in[31];
    float* out = (float*)d_out;

    k_tok<<<512, 128>>>(tf, Wt, bt);
    k_S1<<<256, 128>>>(ms1);
    k_S0<<<128, 256>>>(ms0);
    k_pconv<<<64, 256>>>(Wc0, bc0, Wc1, bc1);
    k_pf<<<4, 128>>>(Wp, bp, Wcat, bcat, Wgate, bgate);
    k_atoms<<<512, 128>>>(lat, Wa, ba);

    cudaFuncSetAttribute(k_inter, cudaFuncAttributeMaxDynamicSharedMemorySize,
                         SMEM_TC_BYTES);
    k_inter<<<148, 256, SMEM_TC_BYTES>>>(Wi, bi, wpe, bpe, wpg, bpg);

    k_final<<<256, 128>>>(lgr, lb, Wgr, bgr, Wb1, bb1, Wb2, bb2, out);
}

// round 5
// speedup vs baseline: 1.0156x; 1.0156x over previous
#include <cuda_runtime.h>
#include <cuda_fp16.h>
#include <cuda_bf16.h>
#include <cstdint>

// ---------------------------------------------------------------------------
// AffinityHead — warp-specialized mma.sync (fp16 x3 split) tensor-core core.
//   Warps 0-7: ldsm + HMMA + epilogue only (no global loads).
//   Warps 8-11: build next atom's M = diag(a)*W tile (double-buffered).
// Scales: T-planes x16, M-planes x256, epilogue x 2^-12 (avoids fp16
// subnormals in the lo planes).
// ---------------------------------------------------------------------------

__device__ __forceinline__ float silu_f(float v) { return v / (1.f + __expf(-v)); }

// ------------------------- scratch (static, no allocs) ---------------------
__device__ float g_tok[4 * 128 * 128];     // [n][j][h]
__device__ float g_S1[4 * 64 * 27];
__device__ float g_S0[4 * 32 * 27];
__device__ float g_p[4 * 256];
__device__ float g_pf[4 * 128];
__device__ float g_atoms[4 * 1024 * 128];  // [n][i][k]
__device__ float g_atom_e[4 * 1024];

// ------------------------------ PTX helpers --------------------------------
__device__ __forceinline__ uint32_t smem_to_u32(const void* p) {
    uint32_t a;
    asm("{ .reg .u64 t; cvta.to.shared.u64 t, %1; cvt.u32.u64 %0, t; }" : "=r"(a) : "l"(p));
    return a;
}

__device__ __forceinline__ void ldsm_x4(uint32_t* r, uint32_t addr) {
    asm volatile("ldmatrix.sync.aligned.m8n8.x4.shared.b16 {%0,%1,%2,%3}, [%4];"
                 : "=r"(r[0]), "=r"(r[1]), "=r"(r[2]), "=r"(r[3]) : "r"(addr));
}

__device__ __forceinline__ void mma_f16(float* d, const uint32_t* a, const uint32_t* b) {
    asm volatile(
        "mma.sync.aligned.m16n8k16.row.col.f32.f16.f16.f32 "
        "{%0,%1,%2,%3}, {%4,%5,%6,%7}, {%8,%9}, {%0,%1,%2,%3};"
        : "+f"(d[0]), "+f"(d[1]), "+f"(d[2]), "+f"(d[3])
        : "r"(a[0]), "r"(a[1]), "r"(a[2]), "r"(a[3]), "r"(b[0]), "r"(b[1]));
}

// ------------------------------ k_tok --------------------------------------
__global__ void k_tok(const float* __restrict__ tf, const float* __restrict__ Wt,
                      const float* __restrict__ bt) {
    int row = blockIdx.x;
    int t = threadIdx.x;
    __shared__ float s[256];
    const float* x = tf + row * 256;
    for (int c = t; c < 256; c += 128) s[c] = silu_f(x[c]);
    __syncthreads();
    float acc = bt[t];
#pragma unroll 8
    for (int c = 0; c < 256; c++) acc += s[c] * Wt[c * 128 + t];
    g_tok[row * 128 + t] = acc;
}

// ------------------------------ k_S1 ----------------------------------------
__global__ void k_S1(const float* __restrict__ x) {
    int nc = blockIdx.x;
    int t = threadIdx.x;
    __shared__ float v[512];
    for (int i = t; i < 512; i += 128) v[i] = silu_f(x[nc * 512 + i]);
    __syncthreads();
    if (t < 27) {
        int kd = t / 9, kh = (t / 3) % 3, kw = t % 3;
        float s = 0.f;
        for (int d = 0; d < 6; d++)
            for (int h = 0; h < 6; h++)
                for (int w = 0; w < 6; w++)
                    s += v[(d + kd) * 64 + (h + kh) * 8 + (w + kw)];
        g_S1[nc * 27 + t] = s;
    }
}

// ------------------------------ k_S0 ----------------------------------------
__global__ void k_S0(const float* __restrict__ x) {
    int nc = blockIdx.x;
    int t = threadIdx.x;
    __shared__ float v[4096];
    __shared__ float rbuf[8];
    for (int i = t; i < 4096; i += 256) v[i] = silu_f(x[nc * 4096 + i]);
    __syncthreads();
    for (int k = 0; k < 27; k++) {
        int kd = k / 9, kh = (k / 3) % 3, kw = k % 3;
        float s = 0.f;
        for (int p = t; p < 2744; p += 256) {
            int d = p / 196;
            int r = p % 196;
            int hh = r / 14, ww = r % 14;
            s += v[(d + kd) * 256 + (hh + kh) * 16 + (ww + kw)];
        }
        for (int off = 16; off > 0; off >>= 1) s += __shfl_down_sync(0xffffffffu, s, off);
        if ((t & 31) == 0) rbuf[t >> 5] = s;
        __syncthreads();
        if (t == 0) {
            float tot = 0.f;
            for (int w = 0; w < 8; w++) tot += rbuf[w];
            g_S0[nc * 27 + k] = tot;
        }
        __syncthreads();
    }
}

// ------------------------------ k_pconv (warp-per-output) -------------------
__global__ void k_pconv(const float* __restrict__ Wc0, const float* __restrict__ bc0,
                        const float* __restrict__ Wc1, const float* __restrict__ bc1) {
    int b = blockIdx.x, t = threadIdx.x;   // 64 blocks x 256 threads
    int n = b >> 4, og = b & 15;
    __shared__ float s1[1728];
    __shared__ float s0[864];
    for (int i = t; i < 1728; i += 256) s1[i] = g_S1[n * 1728 + i];
    for (int i = t; i < 864; i += 256) s0[i] = g_S0[n * 864 + i];
    __syncthreads();
    int w = t >> 5, lane = t & 31;
    int o = og * 8 + w;
    float a0 = 0.f;
    for (int x = lane; x < 1728; x += 32) a0 += s1[x] * Wc0[o * 1728 + x];
    float a1 = 0.f;
    for (int x = lane; x < 864; x += 32) a1 += s0[x] * Wc1[o * 864 + x];
#pragma unroll
    for (int off = 16; off > 0; off >>= 1) {
        a0 += __shfl_down_sync(0xffffffffu, a0, off);
        a1 += __shfl_down_sync(0xffffffffu, a1, off);
    }
    if (lane == 0) {
        g_p[n * 256 + o] = a0 * (1.f / 216.f) + bc0[o];
        g_p[n * 256 + 128 + o] = a1 * (1.f / 2744.f) + bc1[o];
    }
}

// ------------------------------ k_pf ----------------------------------------
__global__ void k_pf(const float* __restrict__ Wp, const float* __restrict__ bp,
                     const float* __restrict__ Wcat, const float* __restrict__ bcat,
                     const float* __restrict__ Wgate, const float* __restrict__ bgate) {
    int n = blockIdx.x, t = threadIdx.x;
    __shared__ float sp[256];
    __shared__ float pin[384];
    for (int c = t; c < 256; c += 128) sp[c] = silu_f(g_p[n * 256 + c]);
    float ts = 0.f;
    for (int j = 0; j < 128; j++) ts += g_tok[(n * 128 + j) * 128 + t];
    __syncthreads();
    float pk = bp[t];
#pragma unroll 4
    for (int c = 0; c < 256; c++) pk += sp[c] * Wp[c * 128 + t];
    pin[t] = pk;
    pin[128 + t] = ts;
    pin[256 + t] = ts * (1.f / 128.f);
    __syncthreads();
    float c1 = bcat[t], g1 = bgate[t];
#pragma unroll 4
    for (int c = 0; c < 384; c++) {
        float z = pin[c];
        c1 += z * Wcat[c * 128 + t];
        g1 += z * Wgate[c * 128 + t];
    }
    g_pf[n * 128 + t] = c1 / (1.f + __expf(-g1));
}

// ------------------------------ k_atoms -------------------------------------
__global__ void k_atoms(const float* __restrict__ la, const float* __restrict__ Wa,
                        const float* __restrict__ ba) {
    int r0 = blockIdx.x * 8;
    int t = threadIdx.x;
    __shared__ float s[8][64];
    for (int i = t; i < 512; i += 128) s[i >> 6][i & 63] = la[r0 * 64 + i];
    __syncthreads();
    float b = ba[t];
    float acc[8];
#pragma unroll
    for (int r = 0; r < 8; r++) acc[r] = b;
    for (int c = 0; c < 64; c++) {
        float w = Wa[c * 128 + t];
#pragma unroll
        for (int r = 0; r < 8; r++) acc[r] += s[r][c] * w;
    }
#pragma unroll
    for (int r = 0; r < 8; r++) g_atoms[(r0 + r) * 128 + t] = acc[r];
}

// ------------------------------ k_inter (warp-specialized) ------------------
#define STH 0                 // tok hi [128][136]h : 34816
#define STL 34816             // tok lo
#define SMB 69632             // M buffers x2 (hi|lo each 34816)
#define MBUF_BYTES 69632
#define SCV 208896            // wpe|wpg|bi : 1536
#define SPE 210432            // peb/pgb : 2048
#define SRED 212480           // 32
#define SSAV 212512           // sav x2 : 1024
#define SMEM_TC_BYTES 213536

#define SCALE_A 16.f
#define SCALE_B 256.f
#define SCALE_INV (1.f / 4096.f)

__global__ void __launch_bounds__(384, 1)
k_inter(const float* __restrict__ Wi, const float* __restrict__ bi,
        const float* __restrict__ wpe, const float* __restrict__ bpe,
        const float* __restrict__ wpg, const float* __restrict__ bpg) {
    extern __shared__ char smc[];
    const uint32_t sb = smem_to_u32(smc);
    float* cv = (float*)(smc + SCV);
    float* peb = (float*)(smc + SPE);        // [2][128]
    float* pgb = peb + 256;                  // [2][128]
    float* red = (float*)(smc + SRED);
    float* sav = (float*)(smc + SSAV);       // [2][128], pre-scaled by SCALE_B

    const int t = threadIdx.x;
    const int wid = t >> 5;
    const int lane = t & 31;

    const int n = blockIdx.x / 37;
    const int grp = blockIdx.x % 37;
    const int i0 = grp * 28;
    const int cnt = min(28, 1024 - i0);
    const float* atomBase = g_atoms + (n * 1024 + i0) * 128;

    const float bpe0 = bpe[0], bpg0 = bpg[0];

    if (t < 256) {
        // consumers: constants + tok hi/lo planes (scaled by SCALE_A)
        if (t < 128) {
            cv[t] = wpe[t];
            cv[128 + t] = wpg[t];
            cv[256 + t] = bi[t];
        }
        const float* tokn = g_tok + n * 16384;
        for (int p = t; p < 8192; p += 256) {
            int j = p >> 6, k2 = p & 63;
            float2 v = *(const float2*)(tokn + j * 128 + 2 * k2);
            float v0 = v.x * SCALE_A, v1 = v.y * SCALE_A;
            __half2 hi = __float22half2_rn(make_float2(v0, v1));
            float r0 = v0 - __low2float(hi);
            float r1 = v1 - __high2float(hi);
            __half2 lo = __float22half2_rn(make_float2(r0, r1));
            uint32_t off = (uint32_t)(j * 272 + 4 * k2);
            *(__half2*)(smc + STH + off) = hi;
            *(__half2*)(smc + STL + off) = lo;
        }
    } else {
        // builders: prologue build of M(0) into buffer 0
        const int tb = t - 256;  // 0..127, handles column h = tb
        sav[tb] = atomBase[tb] * SCALE_B;
        asm volatile("bar.sync 2, 128;" ::: "memory");
        char* mb = smc + SMB;
        float a0 = 0.f, a1 = 0.f;
#pragma unroll 4
        for (int u = 0; u < 64; u++) {
            a0 = sav[2 * u];
            a1 = sav[2 * u + 1];
            float v0 = a0 * Wi[(2 * u) * 128 + tb];
            float v1 = a1 * Wi[(2 * u + 1) * 128 + tb];
            __half2 hi = __float22half2_rn(make_float2(v0, v1));
            float r0 = v0 - __low2float(hi);
            float r1 = v1 - __high2float(hi);
            __half2 lo = __float22half2_rn(make_float2(r0, r1));
            uint32_t off = (uint32_t)(tb * 272 + u * 4);
            *(__half2*)(smc + SMB + off) = hi;
            *(__half2*)(smc + SMB + 34816 + off) = lo;
        }
        (void)mb;
    }
    __syncthreads();

    // ---- per-warp tile / ldmatrix lane addresses (consumers) ----
    const int j0 = (wid & 3) * 32;
    const int h0 = (wid >> 2) * 64;
    const int aRow = lane & 15;
    const int aK = (lane >> 4) << 3;
    const uint32_t aOffH = sb + STH + (uint32_t)((j0 + aRow) * 272 + aK * 2);
    const uint32_t aOffL = sb + STL + (uint32_t)((j0 + aRow) * 272 + aK * 2);
    const int bRow = ((lane >> 4) << 3) + (lane & 7);
    const int bK = ((lane >> 3) & 1) << 3;
    const uint32_t bLane = (uint32_t)((h0 + bRow) * 272 + bK * 2);

    for (int a = 0; a < cnt; a++) {
        if (t < 256) {
            const uint32_t bBaseH = sb + SMB + (uint32_t)((a & 1) * MBUF_BYTES) + bLane;
            const uint32_t bBaseL = bBaseH + 34816;

            float acc[2][8][4];
#pragma unroll
            for (int mt = 0; mt < 2; mt++)
#pragma unroll
                for (int nt = 0; nt < 8; nt++)
#pragma unroll
                    for (int e = 0; e < 4; e++) acc[mt][nt][e] = 0.f;

#pragma unroll
            for (int ks = 0; ks < 8; ks++) {
                const uint32_t ko = (uint32_t)(ks * 32);
                uint32_t aH[2][4], aL[2][4], bH[4][4], bL[4][4];
                ldsm_x4(aH[0], aOffH + ko);
                ldsm_x4(aH[1], aOffH + 4352 + ko);
                ldsm_x4(aL[0], aOffL + ko);
                ldsm_x4(aL[1], aOffL + 4352 + ko);
#pragma unroll
                for (int ng = 0; ng < 4; ng++) {
                    ldsm_x4(bH[ng], bBaseH + (uint32_t)(ng * 4352) + ko);
                    ldsm_x4(bL[ng], bBaseL + (uint32_t)(ng * 4352) + ko);
                }
#pragma unroll
                for (int mt = 0; mt < 2; mt++) {
#pragma unroll
                    for (int ng = 0; ng < 4; ng++) {
                        mma_f16(acc[mt][2 * ng], aH[mt], bH[ng]);
                        mma_f16(acc[mt][2 * ng + 1], aH[mt], bH[ng] + 2);
                        mma_f16(acc[mt][2 * ng], aH[mt], bL[ng]);
                        mma_f16(acc[mt][2 * ng + 1], aH[mt], bL[ng] + 2);
                        mma_f16(acc[mt][2 * ng], aL[mt], bH[ng]);
                        mma_f16(acc[mt][2 * ng + 1], aL[mt], bH[ng] + 2);
                    }
                }
            }

            // ---- epilogue: unscale + lrelu + pe/pg dots ----
            float pe[4] = {0.f, 0.f, 0.f, 0.f}, pg[4] = {0.f, 0.f, 0.f, 0.f};
#pragma unroll
            for (int nt = 0; nt < 8; nt++) {
#pragma unroll
                for (int c = 0; c < 2; c++) {
                    const int h = h0 + 8 * nt + 2 * (lane & 3) + c;
                    const float wpeh = cv[h];
                    const float wpgh = cv[128 + h];
                    const float bih = cv[256 + h];
#pragma unroll
                    for (int mt = 0; mt < 2; mt++) {
#pragma unroll
                        for (int hf = 0; hf < 2; hf++) {
                            float v = acc[mt][nt][hf * 2 + c] * SCALE_INV + bih;
                            v = (v > 0.f) ? v : 0.01f * v;
                            pe[mt * 2 + hf] += v * wpeh;
                            pg[mt * 2 + hf] += v * wpgh;
                        }
                    }
                }
            }
#pragma unroll
            for (int rs = 0; rs < 4; rs++) {
#pragma unroll
                for (int off = 1; off < 4; off <<= 1) {
                    pe[rs] += __shfl_xor_sync(0xffffffffu, pe[rs], off);
                    pg[rs] += __shfl_xor_sync(0xffffffffu, pg[rs], off);
                }
            }
            if ((lane & 3) == 0) {
                const int wx = wid >> 2;
#pragma unroll
                for (int mt = 0; mt < 2; mt++)
#pragma unroll
                    for (int hf = 0; hf < 2; hf++) {
                        int j = j0 + 16 * mt + 8 * hf + (lane >> 2);
                        peb[wx * 128 + j] = pe[mt * 2 + hf];
                        pgb[wx * 128 + j] = pg[mt * 2 + hf];
                    }
            }
            asm volatile("bar.sync 1, 256;" ::: "memory");
            if (t < 128) {
                float spe = peb[t] + peb[128 + t] + bpe0;
                float spg = pgb[t] + pgb[128 + t] + bpg0;
                float sj = spe / (1.f + __expf(-spg));
#pragma unroll
                for (int off = 16; off > 0; off >>= 1)
                    sj += __shfl_xor_sync(0xffffffffu, sj, off);
                if (lane == 0) red[wid] = sj;
            }
            asm volatile("bar.sync 1, 256;" ::: "memory");
            if (t == 0) g_atom_e[n * 1024 + i0 + a] = red[0] + red[1] + red[2] + red[3];
        } else if (a + 1 < cnt) {
            // builders: build M(a+1) into the other buffer
            const int tb = t - 256;
            float* savN = sav + ((a + 1) & 1) * 128;
            savN[tb] = atomBase[(a + 1) * 128 + tb] * SCALE_B;
            asm volatile("bar.sync 2, 128;" ::: "memory");
            char* mbN = smc + SMB + ((a + 1) & 1) * MBUF_BYTES;
#pragma unroll 4
            for (int u = 0; u < 64; u++) {
                float v0 = savN[2 * u] * Wi[(2 * u) * 128 + tb];
                float v1 = savN[2 * u + 1] * Wi[(2 * u + 1) * 128 + tb];
                __half2 hi = __float22half2_rn(make_float2(v0, v1));
                float r0 = v0 - __low2float(hi);
                float r1 = v1 - __high2float(hi);
                __half2 lo = __float22half2_rn(make_float2(r0, r1));
                uint32_t off = (uint32_t)(tb * 272 + u * 4);
                *(__half2*)(mbN + off) = hi;
                *(__half2*)(mbN + 34816 + off) = lo;
            }
        }
        __syncthreads();
    }
}

// ------------------------------ k_final -------------------------------------
__global__ void k_final(const float* __restrict__ lgr, const int* __restrict__ lb,
                        const float* __restrict__ Wgr, const float* __restrict__ bgr,
                        const float* __restrict__ Wb1, const float* __restrict__ bb1,
                        const float* __restrict__ Wb2, const float* __restrict__ bb2,
                        float* __restrict__ out) {
    int n = blockIdx.x >> 6, g = blockIdx.x & 63, t = threadIdx.x;
    __shared__ float z[256];
    __shared__ float lg[64];
    __shared__ float red[8];
    if (t < 64) lg[t] = lgr[(n * 64 + g) * 64 + t];
    z[t] = g_pf[n * 128 + t];
    __syncthreads();
    float gf = bgr[t];
#pragma unroll 4
    for (int c = 0; c < 64; c++) gf += lg[c] * Wgr[c * 128 + t];
    z[128 + t] = gf;
    __syncthreads();
    float h = bb1[t];
#pragma unroll 4
    for (int c = 0; c < 256; c++) h += z[c] * Wb1[c * 128 + t];
    h = (h > 0.f) ? h : 0.01f * h;
    float part = h * Wb2[t];
    float seg = 0.f;
    for (int a = t; a < 1024; a += 128) {
        if (lb[a] == g) seg += g_atom_e[n * 1024 + a];
    }
#pragma unroll
    for (int off = 16; off > 0; off >>= 1) {
        part += __shfl_down_sync(0xffffffffu, part, off);
        seg += __shfl_down_sync(0xffffffffu, seg, off);
    }
    int wid = t >> 5;
    if ((t & 31) == 0) {
        red[wid] = part;
        red[4 + wid] = seg;
    }
    __syncthreads();
    if (t == 0) {
        float bias = red[0] + red[1] + red[2] + red[3] + bb2[0];
        float segs = red[4] + red[5] + red[6] + red[7];
        out[n * 64 + g] = segs + bias;
    }
}

// ------------------------------ launch --------------------------------------
extern "C" void kernel_launch(void* const* d_in, const int* in_sizes, int n_in,
                              void* d_out, int out_size) {
    const float* ms0 = (const float*)d_in[0];
    const float* ms1 = (const float*)d_in[1];
    const float* tf = (const float*)d_in[2];
    const float* lat = (const float*)d_in[3];
    const float* lgr = (const float*)d_in[4];
    const int* lb = (const int*)d_in[5];
    const float* Wt = (const float*)d_in[6];
    const float* bt = (const float*)d_in[7];
    const float* Wc0 = (const float*)d_in[8];
    const float* bc0 = (const float*)d_in[9];
    const float* Wc1 = (const float*)d_in[10];
    const float* bc1 = (const float*)d_in[11];
    const float* Wp = (const float*)d_in[12];
    const float* bp = (const float*)d_in[13];
    const float* Wcat = (const float*)d_in[14];
    const float* bcat = (const float*)d_in[15];
    const float* Wgate = (const float*)d_in[16];
    const float* bgate = (const float*)d_in[17];
    const float* Wa = (const float*)d_in[18];
    const float* ba = (const float*)d_in[19];
    const float* Wgr = (const float*)d_in[20];
    const float* bgr = (const float*)d_in[21];
    const float* Wb1 = (const float*)d_in[22];
    const float* bb1 = (const float*)d_in[23];
    const float* Wb2 = (const float*)d_in[24];
    const float* bb2 = (const float*)d_in[25];
    const float* Wi = (const float*)d_in[26];
    const float* bi = (const float*)d_in[27];
    const float* wpe = (const float*)d_in[28];
    const float* bpe = (const float*)d_in[29];
    const float* wpg = (const float*)d_in[30];
    const float* bpg = (const float*)d_in[31];
    float* out = (float*)d_out;

    k_tok<<<512, 128>>>(tf, Wt, bt);
    k_S1<<<256, 128>>>(ms1);
    k_S0<<<128, 256>>>(ms0);
    k_pconv<<<64, 256>>>(Wc0, bc0, Wc1, bc1);
    k_pf<<<4, 128>>>(Wp, bp, Wcat, bcat, Wgate, bgate);
    k_atoms<<<512, 128>>>(lat, Wa, ba);

    cudaFuncSetAttribute(k_inter, cudaFuncAttributeMaxDynamicSharedMemorySize,
                         SMEM_TC_BYTES);
    k_inter<<<148, 384, SMEM_TC_BYTES>>>(Wi, bi, wpe, bpe, wpg, bpg);

    k_final<<<256, 128>>>(lgr, lb, Wgr, bgr, Wb1, bb1, Wb2, bb2, out);
}

// round 6
// speedup vs baseline: 1.0793x; 1.0627x over previous
#include <cuda_runtime.h>
#include <cuda_fp16.h>
#include <cstdint>

// ---------------------------------------------------------------------------
// AffinityHead — mma.sync fp16x3 split GEMM core with SW128-swizzled smem
// (conflict-free ldsm + conflict-free M-tile builds from staged W^T).
// ---------------------------------------------------------------------------

__device__ __forceinline__ float silu_f(float v) { return v / (1.f + __expf(-v)); }

// ------------------------- scratch (static, no allocs) ---------------------
__device__ float g_tok[4 * 128 * 128];     // [n][j][h]
__device__ float g_S1[4 * 64 * 27];
__device__ float g_S0[4 * 32 * 27];
__device__ float g_p[4 * 256];
__device__ float g_pf[4 * 128];
__device__ float g_atoms[4 * 1024 * 128];  // [n][i][k]
__device__ float g_atom_e[4 * 1024];

// ------------------------------ PTX helpers --------------------------------
__device__ __forceinline__ uint32_t smem_to_u32(const void* p) {
    uint32_t a;
    asm("{ .reg .u64 t; cvta.to.shared.u64 t, %1; cvt.u32.u64 %0, t; }" : "=r"(a) : "l"(p));
    return a;
}

__device__ __forceinline__ void ldsm_x4(uint32_t* r, uint32_t addr) {
    asm volatile("ldmatrix.sync.aligned.m8n8.x4.shared.b16 {%0,%1,%2,%3}, [%4];"
                 : "=r"(r[0]), "=r"(r[1]), "=r"(r[2]), "=r"(r[3]) : "r"(addr));
}

__device__ __forceinline__ void mma_f16(float* d, const uint32_t* a, const uint32_t* b) {
    asm volatile(
        "mma.sync.aligned.m16n8k16.row.col.f32.f16.f16.f32 "
        "{%0,%1,%2,%3}, {%4,%5,%6,%7}, {%8,%9}, {%0,%1,%2,%3};"
        : "+f"(d[0]), "+f"(d[1]), "+f"(d[2]), "+f"(d[3])
        : "r"(a[0]), "r"(a[1]), "r"(a[2]), "r"(a[3]), "r"(b[0]), "r"(b[1]));
}

// SW128 blocked-atom swizzled byte offset for a [128 rows][128 halves] plane
// (plane = 32768 B). k is the half index (0..127), must be even for half2.
__device__ __forceinline__ uint32_t swz(int row, int k) {
    uint32_t off = (uint32_t)(((k >> 6) << 14) + ((row >> 3) << 10) +
                              ((row & 7) << 7) + ((k & 63) << 1));
    return off ^ (uint32_t)((row & 7) << 4);
}

// ------------------------------ k_tok --------------------------------------
__global__ void k_tok(const float* __restrict__ tf, const float* __restrict__ Wt,
                      const float* __restrict__ bt) {
    int row = blockIdx.x;
    int t = threadIdx.x;
    __shared__ float s[256];
    const float* x = tf + row * 256;
    for (int c = t; c < 256; c += 128) s[c] = silu_f(x[c]);
    __syncthreads();
    float acc = bt[t];
#pragma unroll 8
    for (int c = 0; c < 256; c++) acc += s[c] * Wt[c * 128 + t];
    g_tok[row * 128 + t] = acc;
}

// ------------------------------ k_S1 ----------------------------------------
__global__ void k_S1(const float* __restrict__ x) {
    int nc = blockIdx.x;
    int t = threadIdx.x;
    __shared__ float v[512];
    for (int i = t; i < 512; i += 128) v[i] = silu_f(x[nc * 512 + i]);
    __syncthreads();
    if (t < 27) {
        int kd = t / 9, kh = (t / 3) % 3, kw = t % 3;
        float s = 0.f;
        for (int d = 0; d < 6; d++)
            for (int h = 0; h < 6; h++)
                for (int w = 0; w < 6; w++)
                    s += v[(d + kd) * 64 + (h + kh) * 8 + (w + kw)];
        g_S1[nc * 27 + t] = s;
    }
}

// ------------------------------ k_S0 ----------------------------------------
__global__ void k_S0(const float* __restrict__ x) {
    int nc = blockIdx.x;
    int t = threadIdx.x;
    __shared__ float v[4096];
    __shared__ float rbuf[8];
    for (int i = t; i < 4096; i += 256) v[i] = silu_f(x[nc * 4096 + i]);
    __syncthreads();
    for (int k = 0; k < 27; k++) {
        int kd = k / 9, kh = (k / 3) % 3, kw = k % 3;
        float s = 0.f;
        for (int p = t; p < 2744; p += 256) {
            int d = p / 196;
            int r = p % 196;
            int hh = r / 14, ww = r % 14;
            s += v[(d + kd) * 256 + (hh + kh) * 16 + (ww + kw)];
        }
        for (int off = 16; off > 0; off >>= 1) s += __shfl_down_sync(0xffffffffu, s, off);
        if ((t & 31) == 0) rbuf[t >> 5] = s;
        __syncthreads();
        if (t == 0) {
            float tot = 0.f;
            for (int w = 0; w < 8; w++) tot += rbuf[w];
            g_S0[nc * 27 + k] = tot;
        }
        __syncthreads();
    }
}

// ------------------------------ k_pconv (warp-per-output) -------------------
__global__ void k_pconv(const float* __restrict__ Wc0, const float* __restrict__ bc0,
                        const float* __restrict__ Wc1, const float* __restrict__ bc1) {
    int b = blockIdx.x, t = threadIdx.x;   // 64 blocks x 256 threads
    int n = b >> 4, og = b & 15;
    __shared__ float s1[1728];
    __shared__ float s0[864];
    for (int i = t; i < 1728; i += 256) s1[i] = g_S1[n * 1728 + i];
    for (int i = t; i < 864; i += 256) s0[i] = g_S0[n * 864 + i];
    __syncthreads();
    int w = t >> 5, lane = t & 31;
    int o = og * 8 + w;
    float a0 = 0.f;
    for (int x = lane; x < 1728; x += 32) a0 += s1[x] * Wc0[o * 1728 + x];
    float a1 = 0.f;
    for (int x = lane; x < 864; x += 32) a1 += s0[x] * Wc1[o * 864 + x];
#pragma unroll
    for (int off = 16; off > 0; off >>= 1) {
        a0 += __shfl_down_sync(0xffffffffu, a0, off);
        a1 += __shfl_down_sync(0xffffffffu, a1, off);
    }
    if (lane == 0) {
        g_p[n * 256 + o] = a0 * (1.f / 216.f) + bc0[o];
        g_p[n * 256 + 128 + o] = a1 * (1.f / 2744.f) + bc1[o];
    }
}

// ------------------------------ k_pf ----------------------------------------
__global__ void k_pf(const float* __restrict__ Wp, const float* __restrict__ bp,
                     const float* __restrict__ Wcat, const float* __restrict__ bcat,
                     const float* __restrict__ Wgate, const float* __restrict__ bgate) {
    int n = blockIdx.x, t = threadIdx.x;
    __shared__ float sp[256];
    __shared__ float pin[384];
    for (int c = t; c < 256; c += 128) sp[c] = silu_f(g_p[n * 256 + c]);
    float ts = 0.f;
    for (int j = 0; j < 128; j++) ts += g_tok[(n * 128 + j) * 128 + t];
    __syncthreads();
    float pk = bp[t];
#pragma unroll 4
    for (int c = 0; c < 256; c++) pk += sp[c] * Wp[c * 128 + t];
    pin[t] = pk;
    pin[128 + t] = ts;
    pin[256 + t] = ts * (1.f / 128.f);
    __syncthreads();
    float c1 = bcat[t], g1 = bgate[t];
#pragma unroll 4
    for (int c = 0; c < 384; c++) {
        float z = pin[c];
        c1 += z * Wcat[c * 128 + t];
        g1 += z * Wgate[c * 128 + t];
    }
    g_pf[n * 128 + t] = c1 / (1.f + __expf(-g1));
}

// ------------------------------ k_atoms -------------------------------------
__global__ void k_atoms(const float* __restrict__ la, const float* __restrict__ Wa,
                        const float* __restrict__ ba) {
    int r0 = blockIdx.x * 8;
    int t = threadIdx.x;
    __shared__ float s[8][64];
    for (int i = t; i < 512; i += 128) s[i >> 6][i & 63] = la[r0 * 64 + i];
    __syncthreads();
    float b = ba[t];
    float acc[8];
#pragma unroll
    for (int r = 0; r < 8; r++) acc[r] = b;
    for (int c = 0; c < 64; c++) {
        float w = Wa[c * 128 + t];
#pragma unroll
        for (int r = 0; r < 8; r++) acc[r] += s[r][c] * w;
    }
#pragma unroll
    for (int r = 0; r < 8; r++) g_atoms[(r0 + r) * 128 + t] = acc[r];
}

// ------------------------------ k_inter -------------------------------------
// smem: A hi/lo planes (32768 each), M hi/lo planes (32768 each),
//       W^T fp32 [128][130] (66560), cv 1536, peb/pgb 2048, red 64, sav 512
#define SA_HI 0
#define SA_LO 32768
#define SM_HI 65536
#define SM_LO 98304
#define SWT 131072
#define SCV 197632
#define SPE 199168
#define SRED 201216
#define SSAV 201280
#define SMEM_TC_BYTES 201792

#define SCALE_A 16.f
#define SCALE_B 256.f
#define SCALE_INV (1.f / 4096.f)

__global__ void __launch_bounds__(256, 1)
k_inter(const float* __restrict__ Wi, const float* __restrict__ bi,
        const float* __restrict__ wpe, const float* __restrict__ bpe,
        const float* __restrict__ wpg, const float* __restrict__ bpg) {
    extern __shared__ char smc[];
    const uint32_t sb = smem_to_u32(smc);
    float* WfT = (float*)(smc + SWT);
    float* cv = (float*)(smc + SCV);
    float* peb = (float*)(smc + SPE);        // [2][128]
    float* pgb = peb + 256;                  // [2][128]
    float* red = (float*)(smc + SRED);
    float* sav = (float*)(smc + SSAV);       // [128], pre-scaled by SCALE_B

    const int t = threadIdx.x;
    const int wid = t >> 5;
    const int lane = t & 31;

    const int n = blockIdx.x / 37;
    const int grp = blockIdx.x % 37;
    const int i0 = grp * 28;
    const int cnt = min(28, 1024 - i0);
    const float* atomBase = g_atoms + (n * 1024 + i0) * 128;
    const float bpe0 = bpe[0], bpg0 = bpg[0];

    // ---- phase 1: stage W^T, constants, sav(0) ----
    for (int idx = t; idx < 16384; idx += 256) {
        int k = idx >> 7, h = idx & 127;
        WfT[h * 130 + k] = Wi[idx];
    }
    if (t < 128) {
        cv[t] = wpe[t];
        cv[128 + t] = wpg[t];
        cv[256 + t] = bi[t];
        sav[t] = atomBase[t] * SCALE_B;
    }
    __syncthreads();

    // ---- phase 2: A planes (scaled tok) + M(0) planes, swizzled ----
    const float* tokn = g_tok + n * 16384;
    for (int p = t; p < 8192; p += 256) {
        int j = p >> 6, k2 = (p & 63) * 2;
        float2 v = *(const float2*)(tokn + j * 128 + k2);
        float v0 = v.x * SCALE_A, v1 = v.y * SCALE_A;
        __half2 hi = __float22half2_rn(make_float2(v0, v1));
        __half2 lo = __float22half2_rn(
            make_float2(v0 - __low2float(hi), v1 - __high2float(hi)));
        uint32_t o = swz(j, k2);
        *(__half2*)(smc + SA_HI + o) = hi;
        *(__half2*)(smc + SA_LO + o) = lo;
    }
    for (int p = t; p < 8192; p += 256) {
        int h = p >> 6, k2 = (p & 63) * 2;
        float2 w = *(const float2*)(WfT + h * 130 + k2);
        float2 a2 = *(const float2*)(sav + k2);
        float v0 = a2.x * w.x, v1 = a2.y * w.y;
        __half2 hi = __float22half2_rn(make_float2(v0, v1));
        __half2 lo = __float22half2_rn(
            make_float2(v0 - __low2float(hi), v1 - __high2float(hi)));
        uint32_t o = swz(h, k2);
        *(__half2*)(smc + SM_HI + o) = hi;
        *(__half2*)(smc + SM_LO + o) = lo;
    }
    __syncthreads();

    // ---- ldsm lane bases (swizzled) ----
    const int j0 = (wid & 3) * 32;
    const int h0 = (wid >> 2) * 64;
    const int aRowG = j0 + (lane & 15);
    const uint32_t kbA = (uint32_t)(((lane >> 4) << 3) << 1);  // 0 or 16 B
    const uint32_t aXor = (uint32_t)((aRowG & 7) << 4);
    const uint32_t aBase = sb + (uint32_t)(((aRowG >> 3) << 10) + ((aRowG & 7) << 7));
    const int bRowG = h0 + ((lane >> 4) << 3) + (lane & 7);
    const uint32_t kbB = (uint32_t)((((lane >> 3) & 1) << 3) << 1);
    const uint32_t bXor = (uint32_t)((bRowG & 7) << 4);
    const uint32_t bBase = sb + (uint32_t)(((bRowG >> 3) << 10) + ((bRowG & 7) << 7));
    uint32_t alow[4], blow[4];
#pragma unroll
    for (int c = 0; c < 4; c++) {
        alow[c] = (((uint32_t)c << 5) + kbA) ^ aXor;
        blow[c] = (((uint32_t)c << 5) + kbB) ^ bXor;
    }

    for (int a = 0; a < cnt; a++) {
        float acc[2][8][4];
#pragma unroll
        for (int mt = 0; mt < 2; mt++)
#pragma unroll
            for (int nt = 0; nt < 8; nt++)
#pragma unroll
                for (int e = 0; e < 4; e++) acc[mt][nt][e] = 0.f;

#pragma unroll
        for (int ks = 0; ks < 8; ks++) {
            const uint32_t pan = (uint32_t)((ks >> 2) << 14);
            const uint32_t ao = pan + alow[ks & 3];
            const uint32_t bo = pan + blow[ks & 3];
            uint32_t aH[2][4], aL[2][4], bH[4][4], bL[4][4];
            ldsm_x4(aH[0], aBase + SA_HI + ao);
            ldsm_x4(aH[1], aBase + SA_HI + 2048 + ao);
            ldsm_x4(aL[0], aBase + SA_LO + ao);
            ldsm_x4(aL[1], aBase + SA_LO + 2048 + ao);
#pragma unroll
            for (int ng = 0; ng < 4; ng++) {
                ldsm_x4(bH[ng], bBase + SM_HI + (uint32_t)(ng * 2048) + bo);
                ldsm_x4(bL[ng], bBase + SM_LO + (uint32_t)(ng * 2048) + bo);
            }
#pragma unroll
            for (int mt = 0; mt < 2; mt++) {
#pragma unroll
                for (int ng = 0; ng < 4; ng++) {
                    mma_f16(acc[mt][2 * ng], aH[mt], bH[ng]);
                    mma_f16(acc[mt][2 * ng + 1], aH[mt], bH[ng] + 2);
                    mma_f16(acc[mt][2 * ng], aH[mt], bL[ng]);
                    mma_f16(acc[mt][2 * ng + 1], aH[mt], bL[ng] + 2);
                    mma_f16(acc[mt][2 * ng], aL[mt], bH[ng]);
                    mma_f16(acc[mt][2 * ng + 1], aL[mt], bH[ng] + 2);
                }
            }
        }

        // ---- epilogue: unscale + lrelu + pe/pg dots ----
        float pe[4] = {0.f, 0.f, 0.f, 0.f}, pg[4] = {0.f, 0.f, 0.f, 0.f};
#pragma unroll
        for (int nt = 0; nt < 8; nt++) {
#pragma unroll
            for (int c = 0; c < 2; c++) {
                const int h = h0 + 8 * nt + 2 * (lane & 3) + c;
                const float wpeh = cv[h];
                const float wpgh = cv[128 + h];
                const float bih = cv[256 + h];
#pragma unroll
                for (int mt = 0; mt < 2; mt++) {
#pragma unroll
                    for (int hf = 0; hf < 2; hf++) {
                        float v = acc[mt][nt][hf * 2 + c] * SCALE_INV + bih;
                        v = (v > 0.f) ? v : 0.01f * v;
                        pe[mt * 2 + hf] += v * wpeh;
                        pg[mt * 2 + hf] += v * wpgh;
                    }
                }
            }
        }
#pragma unroll
        for (int rs = 0; rs < 4; rs++) {
#pragma unroll
            for (int off = 1; off < 4; off <<= 1) {
                pe[rs] += __shfl_xor_sync(0xffffffffu, pe[rs], off);
                pg[rs] += __shfl_xor_sync(0xffffffffu, pg[rs], off);
            }
        }
        if ((lane & 3) == 0) {
            const int wx = wid >> 2;
#pragma unroll
            for (int mt = 0; mt < 2; mt++)
#pragma unroll
                for (int hf = 0; hf < 2; hf++) {
                    int j = j0 + 16 * mt + 8 * hf + (lane >> 2);
                    peb[wx * 128 + j] = pe[mt * 2 + hf];
                    pgb[wx * 128 + j] = pg[mt * 2 + hf];
                }
        }
        __syncthreads();

        if (t < 128) {
            float spe = peb[t] + peb[128 + t] + bpe0;
            float spg = pgb[t] + pgb[128 + t] + bpg0;
            float sj = spe / (1.f + __expf(-spg));
#pragma unroll
            for (int off = 16; off > 0; off >>= 1)
                sj += __shfl_xor_sync(0xffffffffu, sj, off);
            if (lane == 0) red[wid] = sj;
        } else if (a + 1 < cnt) {
            sav[t - 128] = atomBase[(a + 1) * 128 + (t - 128)] * SCALE_B;
        }
        __syncthreads();

        if (t == 0) g_atom_e[n * 1024 + i0 + a] = red[0] + red[1] + red[2] + red[3];
        if (a + 1 < cnt) {
            // build next M planes (conflict-free: warps sweep k at fixed h)
            for (int p = t; p < 8192; p += 256) {
                int h = p >> 6, k2 = (p & 63) * 2;
                float2 w = *(const float2*)(WfT + h * 130 + k2);
                float2 a2 = *(const float2*)(sav + k2);
                float v0 = a2.x * w.x, v1 = a2.y * w.y;
                __half2 hi = __float22half2_rn(make_float2(v0, v1));
                __half2 lo = __float22half2_rn(
                    make_float2(v0 - __low2float(hi), v1 - __high2float(hi)));
                uint32_t o = swz(h, k2);
                *(__half2*)(smc + SM_HI + o) = hi;
                *(__half2*)(smc + SM_LO + o) = lo;
            }
        }
        __syncthreads();
    }
}

// ------------------------------ k_final -------------------------------------
__global__ void k_final(const float* __restrict__ lgr, const int* __restrict__ lb,
                        const float* __restrict__ Wgr, const float* __restrict__ bgr,
                        const float* __restrict__ Wb1, const float* __restrict__ bb1,
                        const float* __restrict__ Wb2, const float* __restrict__ bb2,
                        float* __restrict__ out) {
    int n = blockIdx.x >> 6, g = blockIdx.x & 63, t = threadIdx.x;
    __shared__ float z[256];
    __shared__ float lg[64];
    __shared__ float red[8];
    if (t < 64) lg[t] = lgr[(n * 64 + g) * 64 + t];
    z[t] = g_pf[n * 128 + t];
    __syncthreads();
    float gf = bgr[t];
#pragma unroll 4
    for (int c = 0; c < 64; c++) gf += lg[c] * Wgr[c * 128 + t];
    z[128 + t] = gf;
    __syncthreads();
    float h = bb1[t];
#pragma unroll 4
    for (int c = 0; c < 256; c++) h += z[c] * Wb1[c * 128 + t];
    h = (h > 0.f) ? h : 0.01f * h;
    float part = h * Wb2[t];
    float seg = 0.f;
    for (int a = t; a < 1024; a += 128) {
        if (lb[a] == g) seg += g_atom_e[n * 1024 + a];
    }
#pragma unroll
    for (int off = 16; off > 0; off >>= 1) {
        part += __shfl_down_sync(0xffffffffu, part, off);
        seg += __shfl_down_sync(0xffffffffu, seg, off);
    }
    int wid = t >> 5;
    if ((t & 31) == 0) {
        red[wid] = part;
        red[4 + wid] = seg;
    }
    __syncthreads();
    if (t == 0) {
        float bias = red[0] + red[1] + red[2] + red[3] + bb2[0];
        float segs = red[4] + red[5] + red[6] + red[7];
        out[n * 64 + g] = segs + bias;
    }
}

// ------------------------------ launch --------------------------------------
extern "C" void kernel_launch(void* const* d_in, const int* in_sizes, int n_in,
                              void* d_out, int out_size) {
    const float* ms0 = (const float*)d_in[0];
    const float* ms1 = (const float*)d_in[1];
    const float* tf = (const float*)d_in[2];
    const float* lat = (const float*)d_in[3];
    const float* lgr = (const float*)d_in[4];
    const int* lb = (const int*)d_in[5];
    const float* Wt = (const float*)d_in[6];
    const float* bt = (const float*)d_in[7];
    const float* Wc0 = (const float*)d_in[8];
    const float* bc0 = (const float*)d_in[9];
    const float* Wc1 = (const float*)d_in[10];
    const float* bc1 = (const float*)d_in[11];
    const float* Wp = (const float*)d_in[12];
    const float* bp = (const float*)d_in[13];
    const float* Wcat = (const float*)d_in[14];
    const float* bcat = (const float*)d_in[15];
    const float* Wgate = (const float*)d_in[16];
    const float* bgate = (const float*)d_in[17];
    const float* Wa = (const float*)d_in[18];
    const float* ba = (const float*)d_in[19];
    const float* Wgr = (const float*)d_in[20];
    const float* bgr = (const float*)d_in[21];
    const float* Wb1 = (const float*)d_in[22];
    const float* bb1 = (const float*)d_in[23];
    const float* Wb2 = (const float*)d_in[24];
    const float* bb2 = (const float*)d_in[25];
    const float* Wi = (const float*)d_in[26];
    const float* bi = (const float*)d_in[27];
    const float* wpe = (const float*)d_in[28];
    const float* bpe = (const float*)d_in[29];
    const float* wpg = (const float*)d_in[30];
    const float* bpg = (const float*)d_in[31];
    float* out = (float*)d_out;

    // Order chosen so k_inter is the 4th launch (ncu -s window lands on it).
    k_tok<<<512, 128>>>(tf, Wt, bt);
    k_atoms<<<512, 128>>>(lat, Wa, ba);
    k_S1<<<256, 128>>>(ms1);

    cudaFuncSetAttribute(k_inter, cudaFuncAttributeMaxDynamicSharedMemorySize,
                         SMEM_TC_BYTES);
    k_inter<<<148, 256, SMEM_TC_BYTES>>>(Wi, bi, wpe, bpe, wpg, bpg);

    k_S0<<<128, 256>>>(ms0);
    k_pconv<<<64, 256>>>(Wc0, bc0, Wc1, bc1);
    k_pf<<<4, 128>>>(Wp, bp, Wcat, bcat, Wgate, bgate);
    k_final<<<256, 128>>>(lgr, lb, Wgr, bgr, Wb1, bb1, Wb2, bb2, out);
}

// round 7
// speedup vs baseline: 1.1036x; 1.0225x over previous
#include <cuda_runtime.h>
#include <cuda_fp16.h>
#include <cstdint>

// ---------------------------------------------------------------------------
// AffinityHead — mma.sync fp16x3 split GEMM core, SW128-swizzled smem,
// 512-thread CTA (16 mma warps, 4/SMSP) for tensor-pipe latency hiding.
// ---------------------------------------------------------------------------

__device__ __forceinline__ float silu_f(float v) { return v / (1.f + __expf(-v)); }

// ------------------------- scratch (static, no allocs) ---------------------
__device__ float g_tok[4 * 128 * 128];     // [n][j][h]
__device__ float g_S1[4 * 64 * 27];
__device__ float g_S0[4 * 32 * 27];
__device__ float g_p[4 * 256];
__device__ float g_pf[4 * 128];
__device__ float g_atoms[4 * 1024 * 128];  // [n][i][k]
__device__ float g_atom_e[4 * 1024];

// ------------------------------ PTX helpers --------------------------------
__device__ __forceinline__ uint32_t smem_to_u32(const void* p) {
    uint32_t a;
    asm("{ .reg .u64 t; cvta.to.shared.u64 t, %1; cvt.u32.u64 %0, t; }" : "=r"(a) : "l"(p));
    return a;
}

__device__ __forceinline__ void ldsm_x4(uint32_t* r, uint32_t addr) {
    asm volatile("ldmatrix.sync.aligned.m8n8.x4.shared.b16 {%0,%1,%2,%3}, [%4];"
                 : "=r"(r[0]), "=r"(r[1]), "=r"(r[2]), "=r"(r[3]) : "r"(addr));
}

__device__ __forceinline__ void mma_f16(float* d, const uint32_t* a, const uint32_t* b) {
    asm volatile(
        "mma.sync.aligned.m16n8k16.row.col.f32.f16.f16.f32 "
        "{%0,%1,%2,%3}, {%4,%5,%6,%7}, {%8,%9}, {%0,%1,%2,%3};"
        : "+f"(d[0]), "+f"(d[1]), "+f"(d[2]), "+f"(d[3])
        : "r"(a[0]), "r"(a[1]), "r"(a[2]), "r"(a[3]), "r"(b[0]), "r"(b[1]));
}

// SW128 blocked-atom swizzled byte offset for a [128 rows][128 halves] plane.
__device__ __forceinline__ uint32_t swz(int row, int k) {
    uint32_t off = (uint32_t)(((k >> 6) << 14) + ((row >> 3) << 10) +
                              ((row & 7) << 7) + ((k & 63) << 1));
    return off ^ (uint32_t)((row & 7) << 4);
}

// ------------------------------ k_tok --------------------------------------
__global__ void k_tok(const float* __restrict__ tf, const float* __restrict__ Wt,
                      const float* __restrict__ bt) {
    int row = blockIdx.x;
    int t = threadIdx.x;
    __shared__ float s[256];
    const float* x = tf + row * 256;
    for (int c = t; c < 256; c += 128) s[c] = silu_f(x[c]);
    __syncthreads();
    float acc = bt[t];
#pragma unroll 8
    for (int c = 0; c < 256; c++) acc += s[c] * Wt[c * 128 + t];
    g_tok[row * 128 + t] = acc;
}

// ------------------------------ k_S1 ----------------------------------------
__global__ void k_S1(const float* __restrict__ x) {
    int nc = blockIdx.x;
    int t = threadIdx.x;
    __shared__ float v[512];
    for (int i = t; i < 512; i += 128) v[i] = silu_f(x[nc * 512 + i]);
    __syncthreads();
    if (t < 27) {
        int kd = t / 9, kh = (t / 3) % 3, kw = t % 3;
        float s = 0.f;
        for (int d = 0; d < 6; d++)
            for (int h = 0; h < 6; h++)
                for (int w = 0; w < 6; w++)
                    s += v[(d + kd) * 64 + (h + kh) * 8 + (w + kw)];
        g_S1[nc * 27 + t] = s;
    }
}

// ------------------------------ k_S0 ----------------------------------------
__global__ void k_S0(const float* __restrict__ x) {
    int nc = blockIdx.x;
    int t = threadIdx.x;
    __shared__ float v[4096];
    __shared__ float rbuf[8];
    for (int i = t; i < 4096; i += 256) v[i] = silu_f(x[nc * 4096 + i]);
    __syncthreads();
    for (int k = 0; k < 27; k++) {
        int kd = k / 9, kh = (k / 3) % 3, kw = k % 3;
        float s = 0.f;
        for (int p = t; p < 2744; p += 256) {
            int d = p / 196;
            int r = p % 196;
            int hh = r / 14, ww = r % 14;
            s += v[(d + kd) * 256 + (hh + kh) * 16 + (ww + kw)];
        }
        for (int off = 16; off > 0; off >>= 1) s += __shfl_down_sync(0xffffffffu, s, off);
        if ((t & 31) == 0) rbuf[t >> 5] = s;
        __syncthreads();
        if (t == 0) {
            float tot = 0.f;
            for (int w = 0; w < 8; w++) tot += rbuf[w];
            g_S0[nc * 27 + k] = tot;
        }
        __syncthreads();
    }
}

// ------------------------------ k_pconv (warp-per-output) -------------------
__global__ void k_pconv(const float* __restrict__ Wc0, const float* __restrict__ bc0,
                        const float* __restrict__ Wc1, const float* __restrict__ bc1) {
    int b = blockIdx.x, t = threadIdx.x;   // 64 blocks x 256 threads
    int n = b >> 4, og = b & 15;
    __shared__ float s1[1728];
    __shared__ float s0[864];
    for (int i = t; i < 1728; i += 256) s1[i] = g_S1[n * 1728 + i];
    for (int i = t; i < 864; i += 256) s0[i] = g_S0[n * 864 + i];
    __syncthreads();
    int w = t >> 5, lane = t & 31;
    int o = og * 8 + w;
    float a0 = 0.f;
    for (int x = lane; x < 1728; x += 32) a0 += s1[x] * Wc0[o * 1728 + x];
    float a1 = 0.f;
    for (int x = lane; x < 864; x += 32) a1 += s0[x] * Wc1[o * 864 + x];
#pragma unroll
    for (int off = 16; off > 0; off >>= 1) {
        a0 += __shfl_down_sync(0xffffffffu, a0, off);
        a1 += __shfl_down_sync(0xffffffffu, a1, off);
    }
    if (lane == 0) {
        g_p[n * 256 + o] = a0 * (1.f / 216.f) + bc0[o];
        g_p[n * 256 + 128 + o] = a1 * (1.f / 2744.f) + bc1[o];
    }
}

// ------------------------------ k_pf ----------------------------------------
__global__ void k_pf(const float* __restrict__ Wp, const float* __restrict__ bp,
                     const float* __restrict__ Wcat, const float* __restrict__ bcat,
                     const float* __restrict__ Wgate, const float* __restrict__ bgate) {
    int n = blockIdx.x, t = threadIdx.x;
    __shared__ float sp[256];
    __shared__ float pin[384];
    for (int c = t; c < 256; c += 128) sp[c] = silu_f(g_p[n * 256 + c]);
    float ts = 0.f;
    for (int j = 0; j < 128; j++) ts += g_tok[(n * 128 + j) * 128 + t];
    __syncthreads();
    float pk = bp[t];
#pragma unroll 4
    for (int c = 0; c < 256; c++) pk += sp[c] * Wp[c * 128 + t];
    pin[t] = pk;
    pin[128 + t] = ts;
    pin[256 + t] = ts * (1.f / 128.f);
    __syncthreads();
    float c1 = bcat[t], g1 = bgate[t];
#pragma unroll 4
    for (int c = 0; c < 384; c++) {
        float z = pin[c];
        c1 += z * Wcat[c * 128 + t];
        g1 += z * Wgate[c * 128 + t];
    }
    g_pf[n * 128 + t] = c1 / (1.f + __expf(-g1));
}

// ------------------------------ k_atoms -------------------------------------
__global__ void k_atoms(const float* __restrict__ la, const float* __restrict__ Wa,
                        const float* __restrict__ ba) {
    int r0 = blockIdx.x * 8;
    int t = threadIdx.x;
    __shared__ float s[8][64];
    for (int i = t; i < 512; i += 128) s[i >> 6][i & 63] = la[r0 * 64 + i];
    __syncthreads();
    float b = ba[t];
    float acc[8];
#pragma unroll
    for (int r = 0; r < 8; r++) acc[r] = b;
    for (int c = 0; c < 64; c++) {
        float w = Wa[c * 128 + t];
#pragma unroll
        for (int r = 0; r < 8; r++) acc[r] += s[r][c] * w;
    }
#pragma unroll
    for (int r = 0; r < 8; r++) g_atoms[(r0 + r) * 128 + t] = acc[r];
}

// ------------------------------ k_inter -------------------------------------
#define SA_HI 0
#define SA_LO 32768
#define SM_HI 65536
#define SM_LO 98304
#define SWT 131072
#define SCV 197632
#define SPE 199168
#define SRED 201216
#define SSAV 201280
#define SMEM_TC_BYTES 201792

#define SCALE_A 16.f
#define SCALE_B 256.f
#define SCALE_INV (1.f / 4096.f)

__global__ void __launch_bounds__(512, 1)
k_inter(const float* __restrict__ Wi, const float* __restrict__ bi,
        const float* __restrict__ wpe, const float* __restrict__ bpe,
        const float* __restrict__ wpg, const float* __restrict__ bpg) {
    extern __shared__ char smc[];
    const uint32_t sb = smem_to_u32(smc);
    float* WfT = (float*)(smc + SWT);
    float* cv = (float*)(smc + SCV);
    float* peb = (float*)(smc + SPE);        // [2][128]
    float* pgb = peb + 256;                  // [2][128]
    float* red = (float*)(smc + SRED);
    float* sav = (float*)(smc + SSAV);       // [128], pre-scaled by SCALE_B

    const int t = threadIdx.x;
    const int wid = t >> 5;
    const int lane = t & 31;

    const int n = blockIdx.x / 37;
    const int grp = blockIdx.x % 37;
    const int i0 = grp * 28;
    const int cnt = min(28, 1024 - i0);
    const float* atomBase = g_atoms + (n * 1024 + i0) * 128;
    const float bpe0 = bpe[0], bpg0 = bpg[0];

    // ---- phase 1: stage W^T, constants, sav(0) ----
    for (int idx = t; idx < 16384; idx += 512) {
        int k = idx >> 7, h = idx & 127;
        WfT[h * 130 + k] = Wi[idx];
    }
    if (t < 128) {
        cv[t] = wpe[t];
        cv[128 + t] = wpg[t];
        cv[256 + t] = bi[t];
        sav[t] = atomBase[t] * SCALE_B;
    }
    __syncthreads();

    // ---- phase 2: A planes (scaled tok) + M(0) planes, swizzled ----
    const float* tokn = g_tok + n * 16384;
    for (int p = t; p < 8192; p += 512) {
        int j = p >> 6, k2 = (p & 63) * 2;
        float2 v = *(const float2*)(tokn + j * 128 + k2);
        float v0 = v.x * SCALE_A, v1 = v.y * SCALE_A;
        __half2 hi = __float22half2_rn(make_float2(v0, v1));
        __half2 lo = __float22half2_rn(
            make_float2(v0 - __low2float(hi), v1 - __high2float(hi)));
        uint32_t o = swz(j, k2);
        *(__half2*)(smc + SA_HI + o) = hi;
        *(__half2*)(smc + SA_LO + o) = lo;
    }
    for (int p = t; p < 8192; p += 512) {
        int h = p >> 6, k2 = (p & 63) * 2;
        float2 w = *(const float2*)(WfT + h * 130 + k2);
        float2 a2 = *(const float2*)(sav + k2);
        float v0 = a2.x * w.x, v1 = a2.y * w.y;
        __half2 hi = __float22half2_rn(make_float2(v0, v1));
        __half2 lo = __float22half2_rn(
            make_float2(v0 - __low2float(hi), v1 - __high2float(hi)));
        uint32_t o = swz(h, k2);
        *(__half2*)(smc + SM_HI + o) = hi;
        *(__half2*)(smc + SM_LO + o) = lo;
    }
    __syncthreads();

    // ---- ldsm lane bases (swizzled). 16 warps: 8 j-tiles x 2 h-halves ----
    const int j0 = (wid & 7) * 16;
    const int h0 = (wid >> 3) * 64;
    const int aRowG = j0 + (lane & 15);
    const uint32_t kbA = (uint32_t)(((lane >> 4) << 3) << 1);  // 0 or 16 B
    const uint32_t aXor = (uint32_t)((aRowG & 7) << 4);
    const uint32_t aBase = sb + (uint32_t)(((aRowG >> 3) << 10) + ((aRowG & 7) << 7));
    const int bRowG = h0 + ((lane >> 4) << 3) + (lane & 7);
    const uint32_t kbB = (uint32_t)((((lane >> 3) & 1) << 3) << 1);
    const uint32_t bXor = (uint32_t)((bRowG & 7) << 4);
    const uint32_t bBase = sb + (uint32_t)(((bRowG >> 3) << 10) + ((bRowG & 7) << 7));
    uint32_t alow[4], blow[4];
#pragma unroll
    for (int c = 0; c < 4; c++) {
        alow[c] = (((uint32_t)c << 5) + kbA) ^ aXor;
        blow[c] = (((uint32_t)c << 5) + kbB) ^ bXor;
    }

    for (int a = 0; a < cnt; a++) {
        float acc[8][4];
#pragma unroll
        for (int nt = 0; nt < 8; nt++)
#pragma unroll
            for (int e = 0; e < 4; e++) acc[nt][e] = 0.f;

#pragma unroll
        for (int ks = 0; ks < 8; ks++) {
            const uint32_t pan = (uint32_t)((ks >> 2) << 14);
            const uint32_t ao = pan + alow[ks & 3];
            const uint32_t bo = pan + blow[ks & 3];
            uint32_t aH[4], aL[4], bH[4][4], bL[4][4];
            ldsm_x4(aH, aBase + SA_HI + ao);
            ldsm_x4(aL, aBase + SA_LO + ao);
#pragma unroll
            for (int ng = 0; ng < 4; ng++) {
                ldsm_x4(bH[ng], bBase + SM_HI + (uint32_t)(ng * 2048) + bo);
                ldsm_x4(bL[ng], bBase + SM_LO + (uint32_t)(ng * 2048) + bo);
            }
#pragma unroll
            for (int ng = 0; ng < 4; ng++) {
                mma_f16(acc[2 * ng], aH, bH[ng]);
                mma_f16(acc[2 * ng + 1], aH, bH[ng] + 2);
                mma_f16(acc[2 * ng], aH, bL[ng]);
                mma_f16(acc[2 * ng + 1], aH, bL[ng] + 2);
                mma_f16(acc[2 * ng], aL, bH[ng]);
                mma_f16(acc[2 * ng + 1], aL, bH[ng] + 2);
            }
        }

        // ---- epilogue: unscale + lrelu + pe/pg dots (16 rows per warp) ----
        float pe[2] = {0.f, 0.f}, pg[2] = {0.f, 0.f};
#pragma unroll
        for (int nt = 0; nt < 8; nt++) {
#pragma unroll
            for (int c = 0; c < 2; c++) {
                const int h = h0 + 8 * nt + 2 * (lane & 3) + c;
                const float wpeh = cv[h];
                const float wpgh = cv[128 + h];
                const float bih = cv[256 + h];
#pragma unroll
                for (int hf = 0; hf < 2; hf++) {
                    float v = acc[nt][hf * 2 + c] * SCALE_INV + bih;
                    v = (v > 0.f) ? v : 0.01f * v;
                    pe[hf] += v * wpeh;
                    pg[hf] += v * wpgh;
                }
            }
        }
#pragma unroll
        for (int hf = 0; hf < 2; hf++) {
#pragma unroll
            for (int off = 1; off < 4; off <<= 1) {
                pe[hf] += __shfl_xor_sync(0xffffffffu, pe[hf], off);
                pg[hf] += __shfl_xor_sync(0xffffffffu, pg[hf], off);
            }
        }
        if ((lane & 3) == 0) {
            const int wx = wid >> 3;
#pragma unroll
            for (int hf = 0; hf < 2; hf++) {
                int j = j0 + 8 * hf + (lane >> 2);
                peb[wx * 128 + j] = pe[hf];
                pgb[wx * 128 + j] = pg[hf];
            }
        }
        __syncthreads();

        if (t < 128) {
            float spe = peb[t] + peb[128 + t] + bpe0;
            float spg = pgb[t] + pgb[128 + t] + bpg0;
            float sj = spe / (1.f + __expf(-spg));
#pragma unroll
            for (int off = 16; off > 0; off >>= 1)
                sj += __shfl_xor_sync(0xffffffffu, sj, off);
            if (lane == 0) red[wid] = sj;
        } else if (t < 256 && a + 1 < cnt) {
            sav[t - 128] = atomBase[(a + 1) * 128 + (t - 128)] * SCALE_B;
        }
        __syncthreads();

        if (t == 0) g_atom_e[n * 1024 + i0 + a] = red[0] + red[1] + red[2] + red[3];
        if (a + 1 < cnt) {
            for (int p = t; p < 8192; p += 512) {
                int h = p >> 6, k2 = (p & 63) * 2;
                float2 w = *(const float2*)(WfT + h * 130 + k2);
                float2 a2 = *(const float2*)(sav + k2);
                float v0 = a2.x * w.x, v1 = a2.y * w.y;
                __half2 hi = __float22half2_rn(make_float2(v0, v1));
                __half2 lo = __float22half2_rn(
                    make_float2(v0 - __low2float(hi), v1 - __high2float(hi)));
                uint32_t o = swz(h, k2);
                *(__half2*)(smc + SM_HI + o) = hi;
                *(__half2*)(smc + SM_LO + o) = lo;
            }
        }
        __syncthreads();
    }
}

// ------------------------------ k_final -------------------------------------
__global__ void k_final(const float* __restrict__ lgr, const int* __restrict__ lb,
                        const float* __restrict__ Wgr, const float* __restrict__ bgr,
                        const float* __restrict__ Wb1, const float* __restrict__ bb1,
                        const float* __restrict__ Wb2, const float* __restrict__ bb2,
                        float* __restrict__ out) {
    int n = blockIdx.x >> 6, g = blockIdx.x & 63, t = threadIdx.x;
    __shared__ float z[256];
    __shared__ float lg[64];
    __shared__ float red[8];
    if (t < 64) lg[t] = lgr[(n * 64 + g) * 64 + t];
    z[t] = g_pf[n * 128 + t];
    __syncthreads();
    float gf = bgr[t];
#pragma unroll 4
    for (int c = 0; c < 64; c++) gf += lg[c] * Wgr[c * 128 + t];
    z[128 + t] = gf;
    __syncthreads();
    float h = bb1[t];
#pragma unroll 4
    for (int c = 0; c < 256; c++) h += z[c] * Wb1[c * 128 + t];
    h = (h > 0.f) ? h : 0.01f * h;
    float part = h * Wb2[t];
    float seg = 0.f;
    for (int a = t; a < 1024; a += 128) {
        if (lb[a] == g) seg += g_atom_e[n * 1024 + a];
    }
#pragma unroll
    for (int off = 16; off > 0; off >>= 1) {
        part += __shfl_down_sync(0xffffffffu, part, off);
        seg += __shfl_down_sync(0xffffffffu, seg, off);
    }
    int wid = t >> 5;
    if ((t & 31) == 0) {
        red[wid] = part;
        red[4 + wid] = seg;
    }
    __syncthreads();
    if (t == 0) {
        float bias = red[0] + red[1] + red[2] + red[3] + bb2[0];
        float segs = red[4] + red[5] + red[6] + red[7];
        out[n * 64 + g] = segs + bias;
    }
}

// ------------------------------ launch --------------------------------------
extern "C" void kernel_launch(void* const* d_in, const int* in_sizes, int n_in,
                              void* d_out, int out_size) {
    const float* ms0 = (const float*)d_in[0];
    const float* ms1 = (const float*)d_in[1];
    const float* tf = (const float*)d_in[2];
    const float* lat = (const float*)d_in[3];
    const float* lgr = (const float*)d_in[4];
    const int* lb = (const int*)d_in[5];
    const float* Wt = (const float*)d_in[6];
    const float* bt = (const float*)d_in[7];
    const float* Wc0 = (const float*)d_in[8];
    const float* bc0 = (const float*)d_in[9];
    const float* Wc1 = (const float*)d_in[10];
    const float* bc1 = (const float*)d_in[11];
    const float* Wp = (const float*)d_in[12];
    const float* bp = (const float*)d_in[13];
    const float* Wcat = (const float*)d_in[14];
    const float* bcat = (const float*)d_in[15];
    const float* Wgate = (const float*)d_in[16];
    const float* bgate = (const float*)d_in[17];
    const float* Wa = (const float*)d_in[18];
    const float* ba = (const float*)d_in[19];
    const float* Wgr = (const float*)d_in[20];
    const float* bgr = (const float*)d_in[21];
    const float* Wb1 = (const float*)d_in[22];
    const float* bb1 = (const float*)d_in[23];
    const float* Wb2 = (const float*)d_in[24];
    const float* bb2 = (const float*)d_in[25];
    const float* Wi = (const float*)d_in[26];
    const float* bi = (const float*)d_in[27];
    const float* wpe = (const float*)d_in[28];
    const float* bpe = (const float*)d_in[29];
    const float* wpg = (const float*)d_in[30];
    const float* bpg = (const float*)d_in[31];
    float* out = (float*)d_out;

    // k_inter is the 4th launch (ncu -s window lands on it).
    k_tok<<<512, 128>>>(tf, Wt, bt);
    k_atoms<<<512, 128>>>(lat, Wa, ba);
    k_S1<<<256, 128>>>(ms1);

    cudaFuncSetAttribute(k_inter, cudaFuncAttributeMaxDynamicSharedMemorySize,
                         SMEM_TC_BYTES);
    k_inter<<<148, 512, SMEM_TC_BYTES>>>(Wi, bi, wpe, bpe, wpg, bpg);

    k_S0<<<128, 256>>>(ms0);
    k_pconv<<<64, 256>>>(Wc0, bc0, Wc1, bc1);
    k_pf<<<4, 128>>>(Wp, bp, Wcat, bcat, Wgate, bgate);
    k_final<<<256, 128>>>(lgr, lb, Wgr, bgr, Wb1, bb1, Wb2, bb2, out);
}